// round 4
// baseline (speedup 1.0000x reference)
#include <cuda_runtime.h>

// Shapes: lx_in/ux_in (32768 rows x 1024 fp32), lc/uc (32768), x_min/x_max (1024).
// Outputs concatenated in d_out: [lx_out | ux_out | lc_out | uc_out].
//
// 256 threads/block, ROWS_PER_BLOCK consecutive rows per block, software
// pipelined: row i+1's loads are issued before row i's reduce/barrier/store,
// so DRAM stays fed through the compute phase. One barrier per row with
// parity double-buffered smem partials. mn/mx live in registers across rows.

#define NROWS 32768
#define INNER 1024
#define NTHREADS 256
#define NWARPS (NTHREADS / 32)
#define ROWS_PER_BLOCK 8
#define NBLOCKS (NROWS / ROWS_PER_BLOCK)

__global__ __launch_bounds__(NTHREADS)
void crown_relu_pipe(const float* __restrict__ lx_in,
                     const float* __restrict__ ux_in,
                     const float* __restrict__ lc_in,
                     const float* __restrict__ uc_in,
                     const float* __restrict__ x_min,
                     const float* __restrict__ x_max,
                     float* __restrict__ lx_out,
                     float* __restrict__ ux_out,
                     float* __restrict__ lc_out,
                     float* __restrict__ uc_out)
{
    const int t    = threadIdx.x;
    const int lane = t & 31;
    const int wid  = t >> 5;
    const int row0 = blockIdx.x * ROWS_PER_BLOCK;

    const float4* __restrict__ lx4 = reinterpret_cast<const float4*>(lx_in);
    const float4* __restrict__ ux4 = reinterpret_cast<const float4*>(ux_in);
    float4* __restrict__ lo4 = reinterpret_cast<float4*>(lx_out);
    float4* __restrict__ uo4 = reinterpret_cast<float4*>(ux_out);

    // Hot 8KB tables -> registers, reused across all rows of this block.
    const float4 mn = __ldg(reinterpret_cast<const float4*>(x_min) + t);
    const float4 mx = __ldg(reinterpret_cast<const float4*>(x_max) + t);

    __shared__ float s_l[2][NWARPS];
    __shared__ float s_u[2][NWARPS];

    // Prologue: load row 0.
    long long off = (long long)row0 * (INNER / 4) + t;
    float4 lv = __ldcs(lx4 + off);
    float4 uv = __ldcs(ux4 + off);

    #pragma unroll
    for (int i = 0; i < ROWS_PER_BLOCK; i++) {
        const int row = row0 + i;
        const long long cur = (long long)row * (INNER / 4) + t;

        // Prefetch next row BEFORE touching this row's reduction: these
        // LDGs are in flight during the shuffle/barrier/store below.
        float4 lvn, uvn;
        if (i + 1 < ROWS_PER_BLOCK) {
            const long long nxt = cur + (INNER / 4);
            lvn = __ldcs(lx4 + nxt);
            uvn = __ldcs(ux4 + nxt);
        }

        // mask_lower*lx == min(lx*mn, lx*mx); mask_upper*ux == max(...).
        float sl = fminf(lv.x * mn.x, lv.x * mx.x)
                 + fminf(lv.y * mn.y, lv.y * mx.y)
                 + fminf(lv.z * mn.z, lv.z * mx.z)
                 + fminf(lv.w * mn.w, lv.w * mx.w);
        float su = fmaxf(uv.x * mn.x, uv.x * mx.x)
                 + fmaxf(uv.y * mn.y, uv.y * mx.y)
                 + fmaxf(uv.z * mn.z, uv.z * mx.z)
                 + fmaxf(uv.w * mn.w, uv.w * mx.w);

        #pragma unroll
        for (int o = 16; o > 0; o >>= 1) {
            sl += __shfl_xor_sync(0xffffffffu, sl, o);
            su += __shfl_xor_sync(0xffffffffu, su, o);
        }

        const int p = i & 1;
        if (lane == 0) { s_l[p][wid] = sl; s_u[p][wid] = su; }
        __syncthreads();   // one barrier per row; parity buffers avoid WAR

        const float lc = lc_in[row];
        const float uc = uc_in[row];
        float l = lc, u = uc;
        #pragma unroll
        for (int w = 0; w < NWARPS; w++) { l += s_l[p][w]; u += s_u[p][w]; }

        const bool  alive = (l >= 0.0f);
        const bool  cross = (l < 0.0f) && (u > 0.0f);
        const float slope = cross ? fminf(fmaxf(u / (u - l), 0.0f), 1.0f) : 1.0f;
        const float fl = alive ? 1.0f : 0.0f;
        const float fu = alive ? 1.0f : (cross ? slope : 0.0f);

        if (t == 0) {
            lc_out[row] = fl * lc;
            uc_out[row] = alive ? uc : (cross ? (slope * uc - slope * l) : 0.0f);
        }

        float4 lo, uo;
        lo.x = fl * lv.x; lo.y = fl * lv.y; lo.z = fl * lv.z; lo.w = fl * lv.w;
        uo.x = fu * uv.x; uo.y = fu * uv.y; uo.z = fu * uv.z; uo.w = fu * uv.w;
        __stcs(lo4 + cur, lo);
        __stcs(uo4 + cur, uo);

        lv = lvn;
        uv = uvn;
    }
}

extern "C" void kernel_launch(void* const* d_in, const int* in_sizes, int n_in,
                              void* d_out, int out_size)
{
    const float* lx_in = (const float*)d_in[0];
    const float* ux_in = (const float*)d_in[1];
    const float* lc_in = (const float*)d_in[2];
    const float* uc_in = (const float*)d_in[3];
    const float* x_min = (const float*)d_in[4];
    const float* x_max = (const float*)d_in[5];

    float* out = (float*)d_out;
    const long long big = (long long)NROWS * INNER;   // 33,554,432
    float* lx_out = out;
    float* ux_out = out + big;
    float* lc_out = out + 2 * big;
    float* uc_out = out + 2 * big + NROWS;

    crown_relu_pipe<<<NBLOCKS, NTHREADS>>>(lx_in, ux_in, lc_in, uc_in,
                                           x_min, x_max,
                                           lx_out, ux_out, lc_out, uc_out);
}